// round 13
// baseline (speedup 1.0000x reference)
#include <cuda_runtime.h>
#include <cuda_bf16.h>
#include <mma.h>
#include <cstdint>
#include <cstddef>

using namespace nvcuda;

// ---------------------------------------------------------------------------
// RQ-VAE forward. Encoder: bit-exact fp32 SIMT with KC=256 chunk folding
// (CONFIRMED R12: matches reference bits, rel_err 1.5e-6). VQ: frozen.
// Decoder: 3xTF32 tensor-core GEMM (hi/lo split, error ~2e-7 — fp32-grade)
// since decoder output only needs rel_err < 1e-3 and sits downstream of the
// bit-exact x_q.
// Output layout (f32): out[B*768] | rq_loss[1] | indices[B*4] | x_q[B*32]
// ---------------------------------------------------------------------------

#define BATCH 65536
#define NSTAGE 4
#define CBSIZE 256
#define EDIM 32

#define SCRATCH_ELTS ((size_t)BATCH * (512 * 3 + 32 + 32) + 16)
__device__ __align__(16) float g_scratch[SCRATCH_ELTS];

__device__ __forceinline__ float tf32q(float x)
{
    uint32_t in = __float_as_uint(x), out;
    asm("cvt.rna.tf32.f32 %0, %1;" : "=r"(out) : "r"(in));
    return __uint_as_float(out);
}

// ---------------------------------------------------------------------------
// Bit-exact fp32 SIMT GEMM (R12 proven binary — DO NOT TOUCH numerics).
// ---------------------------------------------------------------------------
template <int BM, int BN, int BK, int TM, int TN, bool RELU, bool HAS_BIAS>
__global__ void __launch_bounds__((BM / TM) * (BN / TN))
gemm_bias(const float* __restrict__ A, int lda,
          const float* __restrict__ W, int ldw,
          const float* __restrict__ bias, float* __restrict__ C,
          int M, int N, int K)
{
    constexpr int THREADS = (BM / TM) * (BN / TN);
    __shared__ __align__(16) float As[BK][BM + 4];
    __shared__ __align__(16) float Ws[BK][BN + 4];

    const int tid = threadIdx.x;
    const int bm = blockIdx.y * BM;
    const int bn = blockIdx.x * BN;

    const int tx = tid % (BN / TN);
    const int ty = tid / (BN / TN);

    float acc[TM][TN];
#pragma unroll
    for (int i = 0; i < TM; i++)
#pragma unroll
        for (int j = 0; j < TN; j++) acc[i][j] = 0.f;

    for (int k0 = 0; k0 < K; k0 += BK) {
        for (int i = tid * 4; i < BM * BK; i += THREADS * 4) {
            int m = i / BK, k = i % BK;
            float4 v = *reinterpret_cast<const float4*>(
                &A[(size_t)(bm + m) * lda + k0 + k]);
            As[k + 0][m] = v.x; As[k + 1][m] = v.y;
            As[k + 2][m] = v.z; As[k + 3][m] = v.w;
        }
        for (int i = tid * 4; i < BN * BK; i += THREADS * 4) {
            int n = i / BK, k = i % BK;
            float4 v = *reinterpret_cast<const float4*>(
                &W[(size_t)(bn + n) * ldw + k0 + k]);
            Ws[k + 0][n] = v.x; Ws[k + 1][n] = v.y;
            Ws[k + 2][n] = v.z; Ws[k + 3][n] = v.w;
        }
        __syncthreads();

#pragma unroll
        for (int kk = 0; kk < BK; kk++) {
            float ra[TM], rw[TN];
#pragma unroll
            for (int i = 0; i < TM; i += 4)
                *reinterpret_cast<float4*>(&ra[i]) =
                    *reinterpret_cast<const float4*>(&As[kk][ty * TM + i]);
#pragma unroll
            for (int j = 0; j < TN; j += 4)
                *reinterpret_cast<float4*>(&rw[j]) =
                    *reinterpret_cast<const float4*>(&Ws[kk][tx * TN + j]);
#pragma unroll
            for (int i = 0; i < TM; i++)
#pragma unroll
                for (int j = 0; j < TN; j++)
                    acc[i][j] = fmaf(ra[i], rw[j], acc[i][j]);
        }
        __syncthreads();
    }

#pragma unroll
    for (int i = 0; i < TM; i++) {
        const size_t m = (size_t)(bm + ty * TM + i);
#pragma unroll
        for (int j = 0; j < TN; j++) {
            const int n = bn + tx * TN + j;
            float v = acc[i][j];
            if (HAS_BIAS) v = __fadd_rn(v, bias[n]);
            if (RELU) v = fmaxf(v, 0.f);
            C[m * N + n] = v;
        }
    }
}

// ---------------------------------------------------------------------------
// Decoder GEMM: 3xTF32 wmma. C = relu(A*W^T + b), fp32-grade accuracy via
// hi/lo split: x = hi + lo (hi = tf32(x)); acc += hi*hi + hi*lo + lo*hi.
// BM=128, BN=64, BK=16; 8 warps, each a 32x32 tile of 2x2 m16n16k8 frags.
// ---------------------------------------------------------------------------
template <bool RELU>
__global__ void __launch_bounds__(256)
gemm_tf32x3(const float* __restrict__ A, int lda,
            const float* __restrict__ W, int ldw,
            const float* __restrict__ bias, float* __restrict__ C,
            int M, int N, int K)
{
    constexpr int BM = 128, BN = 64, BK = 16, LDS = 24;
    __shared__ float Ah[BM][LDS], Al[BM][LDS];
    __shared__ float Bh[BN][LDS], Bl[BN][LDS];
    __shared__ float Cbuf[8][16 * 16];

    const int tid = threadIdx.x;
    const int wid = tid / 32;
    const int lane = tid % 32;
    const int wm = wid / 2;   // 0..3
    const int wn = wid % 2;   // 0..1
    const int bm = blockIdx.y * BM;
    const int bn = blockIdx.x * BN;

    wmma::fragment<wmma::accumulator, 16, 16, 8, float> acc[2][2];
#pragma unroll
    for (int i = 0; i < 2; i++)
#pragma unroll
        for (int j = 0; j < 2; j++) wmma::fill_fragment(acc[i][j], 0.f);

    for (int k0 = 0; k0 < K; k0 += BK) {
        // A tile: BM x BK, hi/lo split
        for (int i = tid * 4; i < BM * BK; i += 256 * 4) {
            int m = i / BK, k = i % BK;
            float4 v = *reinterpret_cast<const float4*>(
                &A[(size_t)(bm + m) * lda + k0 + k]);
            float hx = tf32q(v.x), hy = tf32q(v.y), hz = tf32q(v.z), hw = tf32q(v.w);
            Ah[m][k + 0] = hx; Al[m][k + 0] = tf32q(v.x - hx);
            Ah[m][k + 1] = hy; Al[m][k + 1] = tf32q(v.y - hy);
            Ah[m][k + 2] = hz; Al[m][k + 2] = tf32q(v.z - hz);
            Ah[m][k + 3] = hw; Al[m][k + 3] = tf32q(v.w - hw);
        }
        // B tile: BN x BK (W rows), hi/lo split
        for (int i = tid * 4; i < BN * BK; i += 256 * 4) {
            int n = i / BK, k = i % BK;
            float4 v = *reinterpret_cast<const float4*>(
                &W[(size_t)(bn + n) * ldw + k0 + k]);
            float hx = tf32q(v.x), hy = tf32q(v.y), hz = tf32q(v.z), hw = tf32q(v.w);
            Bh[n][k + 0] = hx; Bl[n][k + 0] = tf32q(v.x - hx);
            Bh[n][k + 1] = hy; Bl[n][k + 1] = tf32q(v.y - hy);
            Bh[n][k + 2] = hz; Bl[n][k + 2] = tf32q(v.z - hz);
            Bh[n][k + 3] = hw; Bl[n][k + 3] = tf32q(v.w - hw);
        }
        __syncthreads();

#pragma unroll
        for (int kk = 0; kk < BK; kk += 8) {
            wmma::fragment<wmma::matrix_a, 16, 16, 8, wmma::precision::tf32,
                           wmma::row_major> ah[2], al[2];
            wmma::fragment<wmma::matrix_b, 16, 16, 8, wmma::precision::tf32,
                           wmma::col_major> bh[2], bl[2];
#pragma unroll
            for (int i = 0; i < 2; i++) {
                wmma::load_matrix_sync(ah[i], &Ah[wm * 32 + i * 16][kk], LDS);
                wmma::load_matrix_sync(al[i], &Al[wm * 32 + i * 16][kk], LDS);
            }
#pragma unroll
            for (int j = 0; j < 2; j++) {
                wmma::load_matrix_sync(bh[j], &Bh[wn * 32 + j * 16][kk], LDS);
                wmma::load_matrix_sync(bl[j], &Bl[wn * 32 + j * 16][kk], LDS);
            }
#pragma unroll
            for (int i = 0; i < 2; i++)
#pragma unroll
                for (int j = 0; j < 2; j++) {
                    wmma::mma_sync(acc[i][j], ah[i], bh[j], acc[i][j]);
                    wmma::mma_sync(acc[i][j], ah[i], bl[j], acc[i][j]);
                    wmma::mma_sync(acc[i][j], al[i], bh[j], acc[i][j]);
                }
        }
        __syncthreads();
    }

    // Epilogue: per-warp staging buffer, bias + relu
#pragma unroll
    for (int i = 0; i < 2; i++)
#pragma unroll
        for (int j = 0; j < 2; j++) {
            wmma::store_matrix_sync(&Cbuf[wid][0], acc[i][j], 16,
                                    wmma::mem_row_major);
            __syncwarp();
#pragma unroll
            for (int t = 0; t < 8; t++) {
                int e = lane + t * 32;
                int r = e >> 4, c = e & 15;
                int gm = bm + wm * 32 + i * 16 + r;
                int gn = bn + wn * 32 + j * 16 + c;
                float v = Cbuf[wid][e] + bias[gn];
                if (RELU) v = fmaxf(v, 0.f);
                C[(size_t)gm * N + gn] = v;
            }
            __syncwarp();
        }
}

// ---------------------------------------------------------------------------
// Chunk folds (bit-exact path)
// ---------------------------------------------------------------------------
__global__ void __launch_bounds__(256)
combine3_relu(float* __restrict__ c0, const float* __restrict__ c1,
              const float* __restrict__ c2, const float* __restrict__ bias,
              int total, int N)
{
    int i = blockIdx.x * blockDim.x + threadIdx.x;
    if (i >= total) return;
    int n = i % N;
    float v = __fadd_rn(__fadd_rn(c0[i], c1[i]), c2[i]);
    v = __fadd_rn(v, bias[n]);
    c0[i] = fmaxf(v, 0.f);
}

__global__ void __launch_bounds__(256)
combine2_relu(float* __restrict__ c0, const float* __restrict__ c1,
              const float* __restrict__ bias, int total, int N)
{
    int i = blockIdx.x * blockDim.x + threadIdx.x;
    if (i >= total) return;
    int n = i % N;
    float v = __fadd_rn(c0[i], c1[i]);
    v = __fadd_rn(v, bias[n]);
    c0[i] = fmaxf(v, 0.f);
}

// ---------------------------------------------------------------------------
// Residual VQ (frozen bit-for-bit since R8/R12 PASS)
// ---------------------------------------------------------------------------
__device__ __forceinline__ float sumsq_neon(const float* v)
{
    float l0 = 0.f, l1 = 0.f, l2 = 0.f, l3 = 0.f;
#pragma unroll
    for (int i = 0; i < EDIM / 4; i++) {
        l0 = __fadd_rn(l0, __fmul_rn(v[4 * i + 0], v[4 * i + 0]));
        l1 = __fadd_rn(l1, __fmul_rn(v[4 * i + 1], v[4 * i + 1]));
        l2 = __fadd_rn(l2, __fmul_rn(v[4 * i + 2], v[4 * i + 2]));
        l3 = __fadd_rn(l3, __fmul_rn(v[4 * i + 3], v[4 * i + 3]));
    }
    return __fadd_rn(__fadd_rn(l0, l1), __fadd_rn(l2, l3));
}

__global__ void __launch_bounds__(256)
vq_kernel(const float* __restrict__ z, const float* __restrict__ codebooks,
          float* __restrict__ xq_aligned, float* __restrict__ xq_out,
          float* __restrict__ idx_out, float* __restrict__ loss_accum)
{
    __shared__ __align__(16) float cb[CBSIZE * EDIM];
    __shared__ float cn[CBSIZE];

    const int tid = threadIdx.x;
    const size_t row = (size_t)blockIdx.x * blockDim.x + tid;

    float r[EDIM], xq[EDIM];
#pragma unroll
    for (int d = 0; d < EDIM; d++) {
        r[d] = z[row * EDIM + d];
        xq[d] = 0.f;
    }

    float lsum[NSTAGE];

    for (int s = 0; s < NSTAGE; s++) {
        __syncthreads();
        for (int i = tid; i < CBSIZE * EDIM / 4; i += blockDim.x)
            reinterpret_cast<float4*>(cb)[i] =
                reinterpret_cast<const float4*>(codebooks + (size_t)s * CBSIZE * EDIM)[i];
        __syncthreads();
        if (tid < CBSIZE)
            cn[tid] = sumsq_neon(&cb[tid * EDIM]);
        __syncthreads();

        float lsq = sumsq_neon(r);

        float best = __int_as_float(0x7f800000);  // +inf
        int bi = 0;
        for (int j = 0; j < CBSIZE; j++) {
            float dot = 0.f;
#pragma unroll
            for (int d = 0; d < EDIM; d++)
                dot = fmaf(r[d], cb[j * EDIM + d], dot);
            float t1 = __fadd_rn(lsq, cn[j]);
            float t2 = __fmul_rn(2.0f, dot);
            float dist = __fsub_rn(t1, t2);
            if (dist < best) { best = dist; bi = j; }
        }

        float ls = 0.f;
#pragma unroll
        for (int d = 0; d < EDIM; d++) {
            float e = cb[bi * EDIM + d];
            float t = __fsub_rn(e, r[d]);
            ls = __fadd_rn(ls, __fmul_rn(t, t));
            float xres = __fadd_rn(r[d], t);
            xq[d] = __fadd_rn(xq[d], xres);
            r[d] = __fsub_rn(r[d], xres);
        }
        lsum[s] = ls;
        idx_out[row * NSTAGE + s] = (float)bi;
    }

#pragma unroll
    for (int d = 0; d < EDIM; d += 4) {
        float4 v = make_float4(xq[d], xq[d + 1], xq[d + 2], xq[d + 3]);
        *reinterpret_cast<float4*>(&xq_aligned[row * EDIM + d]) = v;
        xq_out[row * EDIM + d + 0] = xq[d + 0];
        xq_out[row * EDIM + d + 1] = xq[d + 1];
        xq_out[row * EDIM + d + 2] = xq[d + 2];
        xq_out[row * EDIM + d + 3] = xq[d + 3];
    }

#pragma unroll
    for (int s = 0; s < NSTAGE; s++) {
        float v = lsum[s];
#pragma unroll
        for (int o = 16; o > 0; o >>= 1)
            v += __shfl_down_sync(0xffffffffu, v, o);
        if ((tid & 31) == 0) atomicAdd(&loss_accum[s], v);
    }
}

__global__ void zero_loss(float* acc)
{
    if (threadIdx.x < NSTAGE) acc[threadIdx.x] = 0.f;
}

__global__ void finalize_loss(const float* __restrict__ acc, float* __restrict__ out_loss)
{
    if (threadIdx.x == 0) {
        float t = acc[0] + acc[1] + acc[2] + acc[3];
        *out_loss = t * (1.25f / (4.0f * (float)BATCH * (float)EDIM));
    }
}

// ---------------------------------------------------------------------------
// Launch
// ---------------------------------------------------------------------------
extern "C" void kernel_launch(void* const* d_in, const int* in_sizes, int n_in,
                              void* d_out, int out_size)
{
    float* scratch = nullptr;
    cudaGetSymbolAddress((void**)&scratch, g_scratch);
    if (!scratch) return;

    const float* x   = (const float*)d_in[0];
    const float* ew0 = (const float*)d_in[1];
    const float* eb0 = (const float*)d_in[2];
    const float* ew1 = (const float*)d_in[3];
    const float* eb1 = (const float*)d_in[4];
    const float* ew2 = (const float*)d_in[5];
    const float* eb2 = (const float*)d_in[6];
    const float* ew3 = (const float*)d_in[7];
    const float* eb3 = (const float*)d_in[8];
    const float* dw0 = (const float*)d_in[9];
    const float* db0 = (const float*)d_in[10];
    const float* dw1 = (const float*)d_in[11];
    const float* db1 = (const float*)d_in[12];
    const float* dw2 = (const float*)d_in[13];
    const float* db2 = (const float*)d_in[14];
    const float* dw3 = (const float*)d_in[15];
    const float* db3 = (const float*)d_in[16];
    const float* cbs = (const float*)d_in[17];

    float* out = (float*)d_out;

    float* slotP0 = scratch;                          // B*512
    float* slotP1 = slotP0 + (size_t)BATCH * 512;     // B*512
    float* slotP2 = slotP1 + (size_t)BATCH * 512;     // B*512
    float* slotZ  = slotP2 + (size_t)BATCH * 512;     // B*32
    float* slotZQ = slotZ + (size_t)BATCH * 32;       // B*32
    float* lacc   = slotZQ + (size_t)BATCH * 32;      // 4

    float* y0  = slotP0;
    float* q0  = slotP1;
    float* q1  = slotP1 + (size_t)BATCH * 256;
    float* y1  = q0;
    float* y2  = slotP2;
    float* z   = slotZ;
    float* zq  = slotZQ;
    float* d1r = slotP2;   // dec0 out (B*128)
    float* d2r = slotP1;   // dec1 out (B*256)
    float* d3r = slotP0;   // dec2 out (B*512)

    float* out_main = out;                            // B*768 (16B aligned)
    float* out_loss = out + (size_t)BATCH * 768;      // 1
    float* out_idx  = out_loss + 1;                   // B*4  (4B aligned)
    float* out_xq   = out_idx + (size_t)BATCH * 4;    // B*32 (4B aligned)

    const int MB = BATCH / 128;  // 512 row-blocks

    zero_loss<<<1, 32>>>(lacc);

    // ---- Encoder (bit-exact, frozen R12 path) ----
    gemm_bias<128, 128, 16, 8, 8, false, false><<<dim3(4, MB), 256>>>(
        x + 0,   768, ew0 + 0,   768, nullptr, slotP0, BATCH, 512, 256);
    gemm_bias<128, 128, 16, 8, 8, false, false><<<dim3(4, MB), 256>>>(
        x + 256, 768, ew0 + 256, 768, nullptr, slotP1, BATCH, 512, 256);
    gemm_bias<128, 128, 16, 8, 8, false, false><<<dim3(4, MB), 256>>>(
        x + 512, 768, ew0 + 512, 768, nullptr, slotP2, BATCH, 512, 256);
    combine3_relu<<<(BATCH * 512 + 255) / 256, 256>>>(
        slotP0, slotP1, slotP2, eb0, BATCH * 512, 512);

    gemm_bias<128, 128, 16, 8, 8, false, false><<<dim3(2, MB), 256>>>(
        y0 + 0,   512, ew1 + 0,   512, nullptr, q0, BATCH, 256, 256);
    gemm_bias<128, 128, 16, 8, 8, false, false><<<dim3(2, MB), 256>>>(
        y0 + 256, 512, ew1 + 256, 512, nullptr, q1, BATCH, 256, 256);
    combine2_relu<<<(BATCH * 256 + 255) / 256, 256>>>(
        q0, q1, eb1, BATCH * 256, 256);

    gemm_bias<128, 128, 16, 8, 8, true, true><<<dim3(1, MB), 256>>>(
        y1, 256, ew2, 256, eb2, y2, BATCH, 128, 256);
    gemm_bias<128, 32, 32, 8, 4, false, true><<<dim3(1, MB), 128>>>(
        y2, 128, ew3, 128, eb3, z, BATCH, 32, 128);

    // ---- Residual VQ (frozen) ----
    vq_kernel<<<BATCH / 256, 256>>>(z, cbs, zq, out_xq, out_idx, lacc);
    finalize_loss<<<1, 32>>>(lacc, out_loss);

    // ---- Decoder: 3xTF32 tensor cores (fp32-grade, flip-safe) ----
    gemm_tf32x3<true><<<dim3(128 / 64, MB), 256>>>(
        zq, 32, dw0, 32, db0, d1r, BATCH, 128, 32);
    gemm_tf32x3<true><<<dim3(256 / 64, MB), 256>>>(
        d1r, 128, dw1, 128, db1, d2r, BATCH, 256, 128);
    gemm_tf32x3<true><<<dim3(512 / 64, MB), 256>>>(
        d2r, 256, dw2, 256, db2, d3r, BATCH, 512, 256);
    gemm_tf32x3<false><<<dim3(768 / 64, MB), 256>>>(
        d3r, 512, dw3, 512, db3, out_main, BATCH, 768, 512);
}

// round 14
// speedup vs baseline: 1.0305x; 1.0305x over previous
#include <cuda_runtime.h>
#include <cuda_bf16.h>
#include <mma.h>
#include <cstdint>
#include <cstddef>

using namespace nvcuda;

// ---------------------------------------------------------------------------
// RQ-VAE forward.
// Encoder: bit-exact fp32 SIMT, KC=256 chunk folding (R12-confirmed bits).
// VQ: frozen. Decoder: dec0/dec1 SIMT (small); dec2/dec3 3xTF32 tensor-core
// GEMM with PRE-SPLIT hi/lo operands and cp.async 2-stage pipeline.
// Output layout (f32): out[B*768] | rq_loss[1] | indices[B*4] | x_q[B*32]
// ---------------------------------------------------------------------------

#define BATCH 65536
#define NSTAGE 4
#define CBSIZE 256
#define EDIM 32

// slots P0,P1,P2 (B*512 each), z, zq (B*32 each), w2/w3 hi+lo, lacc
#define W2_ELTS (512 * 256)
#define W3_ELTS (768 * 512)
#define SCRATCH_ELTS ((size_t)BATCH * 1600 + 2 * (W2_ELTS + W3_ELTS) + 32)
__device__ __align__(16) float g_scratch[SCRATCH_ELTS];

__device__ __forceinline__ float tf32q(float x)
{
    uint32_t in = __float_as_uint(x), out;
    asm("cvt.rna.tf32.f32 %0, %1;" : "=r"(out) : "r"(in));
    return __uint_as_float(out);
}

__device__ __forceinline__ void cp_async16(uint32_t smem_addr, const void* gptr)
{
    asm volatile("cp.async.cg.shared.global [%0], [%1], 16;\n"
                 :: "r"(smem_addr), "l"(gptr));
}

// ---------------------------------------------------------------------------
// Bit-exact fp32 SIMT GEMM (R12-proven numerics). SPLIT: epilogue emits
// hi=tf32q(v), lo=tf32q(v-hi) into C / C2 (for feeding the tf32x3 kernel).
// ---------------------------------------------------------------------------
template <int BM, int BN, int BK, int TM, int TN, bool RELU, bool HAS_BIAS,
          bool SPLIT>
__global__ void __launch_bounds__((BM / TM) * (BN / TN))
gemm_bias(const float* __restrict__ A, int lda,
          const float* __restrict__ W, int ldw,
          const float* __restrict__ bias, float* __restrict__ C,
          float* __restrict__ C2, int M, int N, int K)
{
    constexpr int THREADS = (BM / TM) * (BN / TN);
    __shared__ __align__(16) float As[BK][BM + 4];
    __shared__ __align__(16) float Ws[BK][BN + 4];

    const int tid = threadIdx.x;
    const int bm = blockIdx.y * BM;
    const int bn = blockIdx.x * BN;

    const int tx = tid % (BN / TN);
    const int ty = tid / (BN / TN);

    float acc[TM][TN];
#pragma unroll
    for (int i = 0; i < TM; i++)
#pragma unroll
        for (int j = 0; j < TN; j++) acc[i][j] = 0.f;

    for (int k0 = 0; k0 < K; k0 += BK) {
        for (int i = tid * 4; i < BM * BK; i += THREADS * 4) {
            int m = i / BK, k = i % BK;
            float4 v = *reinterpret_cast<const float4*>(
                &A[(size_t)(bm + m) * lda + k0 + k]);
            As[k + 0][m] = v.x; As[k + 1][m] = v.y;
            As[k + 2][m] = v.z; As[k + 3][m] = v.w;
        }
        for (int i = tid * 4; i < BN * BK; i += THREADS * 4) {
            int n = i / BK, k = i % BK;
            float4 v = *reinterpret_cast<const float4*>(
                &W[(size_t)(bn + n) * ldw + k0 + k]);
            Ws[k + 0][n] = v.x; Ws[k + 1][n] = v.y;
            Ws[k + 2][n] = v.z; Ws[k + 3][n] = v.w;
        }
        __syncthreads();

#pragma unroll
        for (int kk = 0; kk < BK; kk++) {
            float ra[TM], rw[TN];
#pragma unroll
            for (int i = 0; i < TM; i += 4)
                *reinterpret_cast<float4*>(&ra[i]) =
                    *reinterpret_cast<const float4*>(&As[kk][ty * TM + i]);
#pragma unroll
            for (int j = 0; j < TN; j += 4)
                *reinterpret_cast<float4*>(&rw[j]) =
                    *reinterpret_cast<const float4*>(&Ws[kk][tx * TN + j]);
#pragma unroll
            for (int i = 0; i < TM; i++)
#pragma unroll
                for (int j = 0; j < TN; j++)
                    acc[i][j] = fmaf(ra[i], rw[j], acc[i][j]);
        }
        __syncthreads();
    }

#pragma unroll
    for (int i = 0; i < TM; i++) {
        const size_t m = (size_t)(bm + ty * TM + i);
#pragma unroll
        for (int j = 0; j < TN; j++) {
            const int n = bn + tx * TN + j;
            float v = acc[i][j];
            if (HAS_BIAS) v = __fadd_rn(v, bias[n]);
            if (RELU) v = fmaxf(v, 0.f);
            if (SPLIT) {
                float h = tf32q(v);
                C[m * N + n] = h;
                C2[m * N + n] = tf32q(v - h);
            } else {
                C[m * N + n] = v;
            }
        }
    }
}

// ---------------------------------------------------------------------------
// tf32 split of a gmem array (for weights): hi = tf32q(v), lo = tf32q(v-hi)
// ---------------------------------------------------------------------------
__global__ void __launch_bounds__(256)
split_tf32(const float* __restrict__ in, float* __restrict__ hi,
           float* __restrict__ lo, int n4)
{
    int i = blockIdx.x * blockDim.x + threadIdx.x;
    if (i >= n4) return;
    float4 v = reinterpret_cast<const float4*>(in)[i];
    float hx = tf32q(v.x), hy = tf32q(v.y), hz = tf32q(v.z), hw = tf32q(v.w);
    reinterpret_cast<float4*>(hi)[i] = make_float4(hx, hy, hz, hw);
    reinterpret_cast<float4*>(lo)[i] = make_float4(
        tf32q(v.x - hx), tf32q(v.y - hy), tf32q(v.z - hz), tf32q(v.w - hw));
}

// ---------------------------------------------------------------------------
// 3xTF32 wmma GEMM, pre-split operands, cp.async 2-stage pipeline.
// C = relu(Ahi*W^T... + b) with acc = Ah*Bh + Ah*Bl + Al*Bh.
// BM=BN=128, BK=16; 256 threads, 8 warps as 4(m)x2(n), warp tile 32x64.
// Dynamic smem: 2 stages x 4 arrays x 128x20 floats = 80 KB.
// ---------------------------------------------------------------------------
template <bool RELU, bool SPLIT>
__global__ void __launch_bounds__(256)
gemm_tf32x3p(const float* __restrict__ Ah_g, const float* __restrict__ Al_g,
             int lda,
             const float* __restrict__ Bh_g, const float* __restrict__ Bl_g,
             int ldw,
             const float* __restrict__ bias, float* __restrict__ C,
             float* __restrict__ C2, int M, int N, int K)
{
    constexpr int BM = 128, BN = 128, BK = 16, LDS = 20;
    constexpr int ARR = 128 * LDS;            // floats per array
    constexpr int OAh = 0, OAl = ARR, OBh = 2 * ARR, OBl = 3 * ARR;
    constexpr int STAGE = 4 * ARR;            // 10240 floats = 40 KB

    extern __shared__ float smem[];

    const int tid = threadIdx.x;
    const int wid = tid / 32;
    const int lane = tid % 32;
    const int wm = wid / 2;    // 0..3 -> 32-row slice
    const int wn = wid % 2;    // 0..1 -> 64-col slice
    const int bm = blockIdx.y * BM;
    const int bn = blockIdx.x * BN;

    const uint32_t sbase = (uint32_t)__cvta_generic_to_shared(smem);

    wmma::fragment<wmma::accumulator, 16, 16, 8, float> acc[2][4];
#pragma unroll
    for (int i = 0; i < 2; i++)
#pragma unroll
        for (int j = 0; j < 4; j++) wmma::fill_fragment(acc[i][j], 0.f);

    auto load_stage = [&](int s, int k0) {
        uint32_t sb = sbase + (uint32_t)(s * STAGE) * 4u;
#pragma unroll
        for (int f = tid; f < 512; f += 256) {
            int row = f >> 2, c = (f & 3) * 4;
            cp_async16(sb + (uint32_t)(OAh + row * LDS + c) * 4u,
                       Ah_g + (size_t)(bm + row) * lda + k0 + c);
            cp_async16(sb + (uint32_t)(OAl + row * LDS + c) * 4u,
                       Al_g + (size_t)(bm + row) * lda + k0 + c);
            cp_async16(sb + (uint32_t)(OBh + row * LDS + c) * 4u,
                       Bh_g + (size_t)(bn + row) * ldw + k0 + c);
            cp_async16(sb + (uint32_t)(OBl + row * LDS + c) * 4u,
                       Bl_g + (size_t)(bn + row) * ldw + k0 + c);
        }
    };

    const int nt = K / BK;
    load_stage(0, 0);
    asm volatile("cp.async.commit_group;\n" ::: "memory");

    for (int t = 0; t < nt; t++) {
        if (t + 1 < nt) {
            load_stage((t + 1) & 1, (t + 1) * BK);
            asm volatile("cp.async.commit_group;\n" ::: "memory");
            asm volatile("cp.async.wait_group 1;\n" ::: "memory");
        } else {
            asm volatile("cp.async.wait_group 0;\n" ::: "memory");
        }
        __syncthreads();

        const float* st = smem + (t & 1) * STAGE;
#pragma unroll
        for (int kk = 0; kk < BK; kk += 8) {
            wmma::fragment<wmma::matrix_a, 16, 16, 8, wmma::precision::tf32,
                           wmma::row_major> ah[2], al[2];
            wmma::fragment<wmma::matrix_b, 16, 16, 8, wmma::precision::tf32,
                           wmma::col_major> bh[4], bl[4];
#pragma unroll
            for (int i = 0; i < 2; i++) {
                wmma::load_matrix_sync(ah[i],
                    &st[OAh + (wm * 32 + i * 16) * LDS + kk], LDS);
                wmma::load_matrix_sync(al[i],
                    &st[OAl + (wm * 32 + i * 16) * LDS + kk], LDS);
            }
#pragma unroll
            for (int j = 0; j < 4; j++) {
                wmma::load_matrix_sync(bh[j],
                    &st[OBh + (wn * 64 + j * 16) * LDS + kk], LDS);
                wmma::load_matrix_sync(bl[j],
                    &st[OBl + (wn * 64 + j * 16) * LDS + kk], LDS);
            }
#pragma unroll
            for (int i = 0; i < 2; i++)
#pragma unroll
                for (int j = 0; j < 4; j++) {
                    wmma::mma_sync(acc[i][j], ah[i], bh[j], acc[i][j]);
                    wmma::mma_sync(acc[i][j], ah[i], bl[j], acc[i][j]);
                    wmma::mma_sync(acc[i][j], al[i], bh[j], acc[i][j]);
                }
        }
        __syncthreads();
    }

    // Epilogue: per-warp smem staging (pipeline drained; smem reusable)
    float* cb = smem + wid * 256;
#pragma unroll
    for (int i = 0; i < 2; i++)
#pragma unroll
        for (int j = 0; j < 4; j++) {
            wmma::store_matrix_sync(cb, acc[i][j], 16, wmma::mem_row_major);
            __syncwarp();
#pragma unroll
            for (int t = 0; t < 8; t++) {
                int e = lane + t * 32;
                int r = e >> 4, c = e & 15;
                size_t gm = (size_t)(bm + wm * 32 + i * 16 + r);
                int gn = bn + wn * 64 + j * 16 + c;
                float v = cb[e] + bias[gn];
                if (RELU) v = fmaxf(v, 0.f);
                if (SPLIT) {
                    float h = tf32q(v);
                    C[gm * N + gn] = h;
                    C2[gm * N + gn] = tf32q(v - h);
                } else {
                    C[gm * N + gn] = v;
                }
            }
            __syncwarp();
        }
}

// ---------------------------------------------------------------------------
// Chunk folds (bit-exact encoder path)
// ---------------------------------------------------------------------------
__global__ void __launch_bounds__(256)
combine3_relu(float* __restrict__ c0, const float* __restrict__ c1,
              const float* __restrict__ c2, const float* __restrict__ bias,
              int total, int N)
{
    int i = blockIdx.x * blockDim.x + threadIdx.x;
    if (i >= total) return;
    int n = i % N;
    float v = __fadd_rn(__fadd_rn(c0[i], c1[i]), c2[i]);
    v = __fadd_rn(v, bias[n]);
    c0[i] = fmaxf(v, 0.f);
}

__global__ void __launch_bounds__(256)
combine2_relu(float* __restrict__ c0, const float* __restrict__ c1,
              const float* __restrict__ bias, int total, int N)
{
    int i = blockIdx.x * blockDim.x + threadIdx.x;
    if (i >= total) return;
    int n = i % N;
    float v = __fadd_rn(c0[i], c1[i]);
    v = __fadd_rn(v, bias[n]);
    c0[i] = fmaxf(v, 0.f);
}

// ---------------------------------------------------------------------------
// Residual VQ (frozen bit-for-bit since R12 PASS)
// ---------------------------------------------------------------------------
__device__ __forceinline__ float sumsq_neon(const float* v)
{
    float l0 = 0.f, l1 = 0.f, l2 = 0.f, l3 = 0.f;
#pragma unroll
    for (int i = 0; i < EDIM / 4; i++) {
        l0 = __fadd_rn(l0, __fmul_rn(v[4 * i + 0], v[4 * i + 0]));
        l1 = __fadd_rn(l1, __fmul_rn(v[4 * i + 1], v[4 * i + 1]));
        l2 = __fadd_rn(l2, __fmul_rn(v[4 * i + 2], v[4 * i + 2]));
        l3 = __fadd_rn(l3, __fmul_rn(v[4 * i + 3], v[4 * i + 3]));
    }
    return __fadd_rn(__fadd_rn(l0, l1), __fadd_rn(l2, l3));
}

__global__ void __launch_bounds__(256)
vq_kernel(const float* __restrict__ z, const float* __restrict__ codebooks,
          float* __restrict__ xq_aligned, float* __restrict__ xq_out,
          float* __restrict__ idx_out, float* __restrict__ loss_accum)
{
    __shared__ __align__(16) float cb[CBSIZE * EDIM];
    __shared__ float cn[CBSIZE];

    const int tid = threadIdx.x;
    const size_t row = (size_t)blockIdx.x * blockDim.x + tid;

    float r[EDIM], xq[EDIM];
#pragma unroll
    for (int d = 0; d < EDIM; d++) {
        r[d] = z[row * EDIM + d];
        xq[d] = 0.f;
    }

    float lsum[NSTAGE];

    for (int s = 0; s < NSTAGE; s++) {
        __syncthreads();
        for (int i = tid; i < CBSIZE * EDIM / 4; i += blockDim.x)
            reinterpret_cast<float4*>(cb)[i] =
                reinterpret_cast<const float4*>(codebooks + (size_t)s * CBSIZE * EDIM)[i];
        __syncthreads();
        if (tid < CBSIZE)
            cn[tid] = sumsq_neon(&cb[tid * EDIM]);
        __syncthreads();

        float lsq = sumsq_neon(r);

        float best = __int_as_float(0x7f800000);  // +inf
        int bi = 0;
        for (int j = 0; j < CBSIZE; j++) {
            float dot = 0.f;
#pragma unroll
            for (int d = 0; d < EDIM; d++)
                dot = fmaf(r[d], cb[j * EDIM + d], dot);
            float t1 = __fadd_rn(lsq, cn[j]);
            float t2 = __fmul_rn(2.0f, dot);
            float dist = __fsub_rn(t1, t2);
            if (dist < best) { best = dist; bi = j; }
        }

        float ls = 0.f;
#pragma unroll
        for (int d = 0; d < EDIM; d++) {
            float e = cb[bi * EDIM + d];
            float t = __fsub_rn(e, r[d]);
            ls = __fadd_rn(ls, __fmul_rn(t, t));
            float xres = __fadd_rn(r[d], t);
            xq[d] = __fadd_rn(xq[d], xres);
            r[d] = __fsub_rn(r[d], xres);
        }
        lsum[s] = ls;
        idx_out[row * NSTAGE + s] = (float)bi;
    }

#pragma unroll
    for (int d = 0; d < EDIM; d += 4) {
        float4 v = make_float4(xq[d], xq[d + 1], xq[d + 2], xq[d + 3]);
        *reinterpret_cast<float4*>(&xq_aligned[row * EDIM + d]) = v;
        xq_out[row * EDIM + d + 0] = xq[d + 0];
        xq_out[row * EDIM + d + 1] = xq[d + 1];
        xq_out[row * EDIM + d + 2] = xq[d + 2];
        xq_out[row * EDIM + d + 3] = xq[d + 3];
    }

#pragma unroll
    for (int s = 0; s < NSTAGE; s++) {
        float v = lsum[s];
#pragma unroll
        for (int o = 16; o > 0; o >>= 1)
            v += __shfl_down_sync(0xffffffffu, v, o);
        if ((tid & 31) == 0) atomicAdd(&loss_accum[s], v);
    }
}

__global__ void zero_loss(float* acc)
{
    if (threadIdx.x < NSTAGE) acc[threadIdx.x] = 0.f;
}

__global__ void finalize_loss(const float* __restrict__ acc, float* __restrict__ out_loss)
{
    if (threadIdx.x == 0) {
        float t = acc[0] + acc[1] + acc[2] + acc[3];
        *out_loss = t * (1.25f / (4.0f * (float)BATCH * (float)EDIM));
    }
}

// ---------------------------------------------------------------------------
// Launch
// ---------------------------------------------------------------------------
extern "C" void kernel_launch(void* const* d_in, const int* in_sizes, int n_in,
                              void* d_out, int out_size)
{
    float* scratch = nullptr;
    cudaGetSymbolAddress((void**)&scratch, g_scratch);
    if (!scratch) return;

    static bool attr_set = false;
    if (!attr_set) {
        cudaFuncSetAttribute(gemm_tf32x3p<true, true>,
                             cudaFuncAttributeMaxDynamicSharedMemorySize, 81920);
        cudaFuncSetAttribute(gemm_tf32x3p<false, false>,
                             cudaFuncAttributeMaxDynamicSharedMemorySize, 81920);
        attr_set = true;
    }

    const float* x   = (const float*)d_in[0];
    const float* ew0 = (const float*)d_in[1];
    const float* eb0 = (const float*)d_in[2];
    const float* ew1 = (const float*)d_in[3];
    const float* eb1 = (const float*)d_in[4];
    const float* ew2 = (const float*)d_in[5];
    const float* eb2 = (const float*)d_in[6];
    const float* ew3 = (const float*)d_in[7];
    const float* eb3 = (const float*)d_in[8];
    const float* dw0 = (const float*)d_in[9];
    const float* db0 = (const float*)d_in[10];
    const float* dw1 = (const float*)d_in[11];
    const float* db1 = (const float*)d_in[12];
    const float* dw2 = (const float*)d_in[13];
    const float* db2 = (const float*)d_in[14];
    const float* dw3 = (const float*)d_in[15];
    const float* db3 = (const float*)d_in[16];
    const float* cbs = (const float*)d_in[17];

    float* out = (float*)d_out;

    float* slotP0 = scratch;                          // B*512
    float* slotP1 = slotP0 + (size_t)BATCH * 512;     // B*512
    float* slotP2 = slotP1 + (size_t)BATCH * 512;     // B*512
    float* slotZ  = slotP2 + (size_t)BATCH * 512;     // B*32
    float* slotZQ = slotZ + (size_t)BATCH * 32;       // B*32
    float* w2hi   = slotZQ + (size_t)BATCH * 32;      // W2
    float* w2lo   = w2hi + W2_ELTS;
    float* w3hi   = w2lo + W2_ELTS;
    float* w3lo   = w3hi + W3_ELTS;
    float* lacc   = w3lo + W3_ELTS;                   // 4

    float* y0   = slotP0;
    float* q0   = slotP1;
    float* q1   = slotP1 + (size_t)BATCH * 256;
    float* y1   = q0;
    float* y2   = slotP2;
    float* z    = slotZ;
    float* zq   = slotZQ;
    float* d1r  = slotP2;                             // dec0 out (B*128)
    float* d2hi = slotP1;                             // dec1 out hi (B*256)
    float* d2lo = slotP1 + (size_t)BATCH * 256;       // dec1 out lo (B*256)
    float* d3hi = slotP0;                             // dec2 out hi (B*512)
    float* d3lo = slotP2;                             // dec2 out lo (B*512)

    float* out_main = out;                            // B*768 (16B aligned)
    float* out_loss = out + (size_t)BATCH * 768;      // 1
    float* out_idx  = out_loss + 1;                   // B*4  (4B aligned)
    float* out_xq   = out_idx + (size_t)BATCH * 4;    // B*32 (4B aligned)

    const int MB = BATCH / 128;  // 512 row-blocks

    zero_loss<<<1, 32>>>(lacc);

    // Split decoder weights for the tf32x3 path (tiny, memory-bound)
    split_tf32<<<(W2_ELTS / 4 + 255) / 256, 256>>>(dw2, w2hi, w2lo, W2_ELTS / 4);
    split_tf32<<<(W3_ELTS / 4 + 255) / 256, 256>>>(dw3, w3hi, w3lo, W3_ELTS / 4);

    // ---- Encoder (bit-exact, frozen R12 path) ----
    gemm_bias<128, 128, 16, 8, 8, false, false, false><<<dim3(4, MB), 256>>>(
        x + 0,   768, ew0 + 0,   768, nullptr, slotP0, nullptr, BATCH, 512, 256);
    gemm_bias<128, 128, 16, 8, 8, false, false, false><<<dim3(4, MB), 256>>>(
        x + 256, 768, ew0 + 256, 768, nullptr, slotP1, nullptr, BATCH, 512, 256);
    gemm_bias<128, 128, 16, 8, 8, false, false, false><<<dim3(4, MB), 256>>>(
        x + 512, 768, ew0 + 512, 768, nullptr, slotP2, nullptr, BATCH, 512, 256);
    combine3_relu<<<(BATCH * 512 + 255) / 256, 256>>>(
        slotP0, slotP1, slotP2, eb0, BATCH * 512, 512);

    gemm_bias<128, 128, 16, 8, 8, false, false, false><<<dim3(2, MB), 256>>>(
        y0 + 0,   512, ew1 + 0,   512, nullptr, q0, nullptr, BATCH, 256, 256);
    gemm_bias<128, 128, 16, 8, 8, false, false, false><<<dim3(2, MB), 256>>>(
        y0 + 256, 512, ew1 + 256, 512, nullptr, q1, nullptr, BATCH, 256, 256);
    combine2_relu<<<(BATCH * 256 + 255) / 256, 256>>>(
        q0, q1, eb1, BATCH * 256, 256);

    gemm_bias<128, 128, 16, 8, 8, true, true, false><<<dim3(1, MB), 256>>>(
        y1, 256, ew2, 256, eb2, y2, nullptr, BATCH, 128, 256);
    gemm_bias<128, 32, 32, 8, 4, false, true, false><<<dim3(1, MB), 128>>>(
        y2, 128, ew3, 128, eb3, z, nullptr, BATCH, 32, 128);

    // ---- Residual VQ (frozen) ----
    vq_kernel<<<BATCH / 256, 256>>>(z, cbs, zq, out_xq, out_idx, lacc);
    finalize_loss<<<1, 32>>>(lacc, out_loss);

    // ---- Decoder ----
    // dec0, dec1: SIMT (small). dec1 epilogue pre-splits its output.
    gemm_bias<128, 128, 16, 8, 8, true, true, false><<<dim3(1, MB), 256>>>(
        zq, 32, dw0, 32, db0, d1r, nullptr, BATCH, 128, 32);
    gemm_bias<128, 128, 16, 8, 8, true, true, true><<<dim3(2, MB), 256>>>(
        d1r, 128, dw1, 128, db1, d2hi, d2lo, BATCH, 256, 128);

    // dec2, dec3: pipelined 3xTF32 tensor cores on pre-split operands.
    gemm_tf32x3p<true, true><<<dim3(512 / 128, MB), 256, 81920>>>(
        d2hi, d2lo, 256, w2hi, w2lo, 256, db2, d3hi, d3lo, BATCH, 512, 256);
    gemm_tf32x3p<false, false><<<dim3(768 / 128, MB), 256, 81920>>>(
        d3hi, d3lo, 512, w3hi, w3lo, 512, db3, out_main, nullptr,
        BATCH, 768, 512);
}

// round 16
// speedup vs baseline: 1.3742x; 1.3335x over previous
#include <cuda_runtime.h>
#include <cuda_bf16.h>
#include <cstdint>
#include <cstddef>

// ---------------------------------------------------------------------------
// RQ-VAE forward, all-SIMT fp32 (bit-exact encoder: KC=256 chunk folding,
// R12-confirmed). GEMMs now use register-staged double buffering: LDG of
// tile t+1 overlaps compute of tile t; one __syncthreads per tile. The
// per-output ascending-k fused-fma chain is unchanged -> bit-identical z.
// Decoder: same SIMT kernel (wmma/mma.sync path abandoned: measured ~65TF/s
// on sm_100a legacy tensor path, slower than SIMT fp32).
// Output layout (f32): out[B*768] | rq_loss[1] | indices[B*4] | x_q[B*32]
// ---------------------------------------------------------------------------

#define BATCH 65536
#define NSTAGE 4
#define CBSIZE 256
#define EDIM 32

#define SCRATCH_ELTS ((size_t)BATCH * (512 * 3 + 32 + 32) + 16)
__device__ __align__(16) float g_scratch[SCRATCH_ELTS];

// ---------------------------------------------------------------------------
// Double-buffered fp32 SIMT GEMM.
// C[m][n] = (relu)( sum_k A[m][k]*W[n][k] (+ bias[n]) )
// Bit-exact accumulation: single fmaf chain per output, k ascending.
// ---------------------------------------------------------------------------
template <int BM, int BN, int BK, int TM, int TN, bool RELU, bool HAS_BIAS>
__global__ void __launch_bounds__((BM / TM) * (BN / TN))
gemm_db(const float* __restrict__ A, int lda,
        const float* __restrict__ W, int ldw,
        const float* __restrict__ bias, float* __restrict__ C,
        int M, int N, int K)
{
    constexpr int THREADS = (BM / TM) * (BN / TN);
    constexpr int A_IT = (BM * BK) / (THREADS * 4);
    constexpr int W_IT = (BN * BK) / (THREADS * 4);

    __shared__ __align__(16) float As[2][BK][BM + 4];
    __shared__ __align__(16) float Ws[2][BK][BN + 4];

    const int tid = threadIdx.x;
    const int bm = blockIdx.y * BM;
    const int bn = blockIdx.x * BN;
    const int tx = tid % (BN / TN);
    const int ty = tid / (BN / TN);

    float4 sa[A_IT], sw[W_IT];

    auto ldg_tile = [&](int k0) {
#pragma unroll
        for (int u = 0; u < A_IT; u++) {
            int i = (tid + u * THREADS) * 4;
            int m = i / BK, k = i % BK;
            sa[u] = *reinterpret_cast<const float4*>(
                &A[(size_t)(bm + m) * lda + k0 + k]);
        }
#pragma unroll
        for (int u = 0; u < W_IT; u++) {
            int i = (tid + u * THREADS) * 4;
            int n = i / BK, k = i % BK;
            sw[u] = *reinterpret_cast<const float4*>(
                &W[(size_t)(bn + n) * ldw + k0 + k]);
        }
    };

    auto sts_tile = [&](int b) {
#pragma unroll
        for (int u = 0; u < A_IT; u++) {
            int i = (tid + u * THREADS) * 4;
            int m = i / BK, k = i % BK;
            As[b][k + 0][m] = sa[u].x; As[b][k + 1][m] = sa[u].y;
            As[b][k + 2][m] = sa[u].z; As[b][k + 3][m] = sa[u].w;
        }
#pragma unroll
        for (int u = 0; u < W_IT; u++) {
            int i = (tid + u * THREADS) * 4;
            int n = i / BK, k = i % BK;
            Ws[b][k + 0][n] = sw[u].x; Ws[b][k + 1][n] = sw[u].y;
            Ws[b][k + 2][n] = sw[u].z; Ws[b][k + 3][n] = sw[u].w;
        }
    };

    float acc[TM][TN];
#pragma unroll
    for (int i = 0; i < TM; i++)
#pragma unroll
        for (int j = 0; j < TN; j++) acc[i][j] = 0.f;

    const int nt = K / BK;
    ldg_tile(0);
    sts_tile(0);
    __syncthreads();

    for (int t = 0; t < nt; t++) {
        if (t + 1 < nt) ldg_tile((t + 1) * BK);  // overlap with compute below

        const int b = t & 1;
#pragma unroll
        for (int kk = 0; kk < BK; kk++) {
            float ra[TM], rw[TN];
#pragma unroll
            for (int i = 0; i < TM; i += 4)
                *reinterpret_cast<float4*>(&ra[i]) =
                    *reinterpret_cast<const float4*>(&As[b][kk][ty * TM + i]);
#pragma unroll
            for (int j = 0; j < TN; j += 4)
                *reinterpret_cast<float4*>(&rw[j]) =
                    *reinterpret_cast<const float4*>(&Ws[b][kk][tx * TN + j]);
#pragma unroll
            for (int i = 0; i < TM; i++)
#pragma unroll
                for (int j = 0; j < TN; j++)
                    acc[i][j] = fmaf(ra[i], rw[j], acc[i][j]);
        }

        if (t + 1 < nt) {
            sts_tile((t + 1) & 1);
            __syncthreads();
        }
    }

#pragma unroll
    for (int i = 0; i < TM; i++) {
        const size_t m = (size_t)(bm + ty * TM + i);
#pragma unroll
        for (int j = 0; j < TN; j++) {
            const int n = bn + tx * TN + j;
            float v = acc[i][j];
            if (HAS_BIAS) v = __fadd_rn(v, bias[n]);
            if (RELU) v = fmaxf(v, 0.f);
            C[m * N + n] = v;
        }
    }
}

// ---------------------------------------------------------------------------
// Chunk folds (bit-exact encoder path, frozen since R12)
// ---------------------------------------------------------------------------
__global__ void __launch_bounds__(256)
combine3_relu(float* __restrict__ c0, const float* __restrict__ c1,
              const float* __restrict__ c2, const float* __restrict__ bias,
              int total, int N)
{
    int i = blockIdx.x * blockDim.x + threadIdx.x;
    if (i >= total) return;
    int n = i % N;
    float v = __fadd_rn(__fadd_rn(c0[i], c1[i]), c2[i]);
    v = __fadd_rn(v, bias[n]);
    c0[i] = fmaxf(v, 0.f);
}

__global__ void __launch_bounds__(256)
combine2_relu(float* __restrict__ c0, const float* __restrict__ c1,
              const float* __restrict__ bias, int total, int N)
{
    int i = blockIdx.x * blockDim.x + threadIdx.x;
    if (i >= total) return;
    int n = i % N;
    float v = __fadd_rn(c0[i], c1[i]);
    v = __fadd_rn(v, bias[n]);
    c0[i] = fmaxf(v, 0.f);
}

// ---------------------------------------------------------------------------
// Residual VQ (frozen bit-for-bit since R12 PASS)
// ---------------------------------------------------------------------------
__device__ __forceinline__ float sumsq_neon(const float* v)
{
    float l0 = 0.f, l1 = 0.f, l2 = 0.f, l3 = 0.f;
#pragma unroll
    for (int i = 0; i < EDIM / 4; i++) {
        l0 = __fadd_rn(l0, __fmul_rn(v[4 * i + 0], v[4 * i + 0]));
        l1 = __fadd_rn(l1, __fmul_rn(v[4 * i + 1], v[4 * i + 1]));
        l2 = __fadd_rn(l2, __fmul_rn(v[4 * i + 2], v[4 * i + 2]));
        l3 = __fadd_rn(l3, __fmul_rn(v[4 * i + 3], v[4 * i + 3]));
    }
    return __fadd_rn(__fadd_rn(l0, l1), __fadd_rn(l2, l3));
}

__global__ void __launch_bounds__(256)
vq_kernel(const float* __restrict__ z, const float* __restrict__ codebooks,
          float* __restrict__ xq_aligned, float* __restrict__ xq_out,
          float* __restrict__ idx_out, float* __restrict__ loss_accum)
{
    __shared__ __align__(16) float cb[CBSIZE * EDIM];
    __shared__ float cn[CBSIZE];

    const int tid = threadIdx.x;
    const size_t row = (size_t)blockIdx.x * blockDim.x + tid;

    float r[EDIM], xq[EDIM];
#pragma unroll
    for (int d = 0; d < EDIM; d++) {
        r[d] = z[row * EDIM + d];
        xq[d] = 0.f;
    }

    float lsum[NSTAGE];

    for (int s = 0; s < NSTAGE; s++) {
        __syncthreads();
        for (int i = tid; i < CBSIZE * EDIM / 4; i += blockDim.x)
            reinterpret_cast<float4*>(cb)[i] =
                reinterpret_cast<const float4*>(codebooks + (size_t)s * CBSIZE * EDIM)[i];
        __syncthreads();
        if (tid < CBSIZE)
            cn[tid] = sumsq_neon(&cb[tid * EDIM]);
        __syncthreads();

        float lsq = sumsq_neon(r);

        float best = __int_as_float(0x7f800000);  // +inf
        int bi = 0;
        for (int j = 0; j < CBSIZE; j++) {
            float dot = 0.f;
#pragma unroll
            for (int d = 0; d < EDIM; d++)
                dot = fmaf(r[d], cb[j * EDIM + d], dot);
            float t1 = __fadd_rn(lsq, cn[j]);
            float t2 = __fmul_rn(2.0f, dot);
            float dist = __fsub_rn(t1, t2);
            if (dist < best) { best = dist; bi = j; }
        }

        float ls = 0.f;
#pragma unroll
        for (int d = 0; d < EDIM; d++) {
            float e = cb[bi * EDIM + d];
            float t = __fsub_rn(e, r[d]);
            ls = __fadd_rn(ls, __fmul_rn(t, t));
            float xres = __fadd_rn(r[d], t);
            xq[d] = __fadd_rn(xq[d], xres);
            r[d] = __fsub_rn(r[d], xres);
        }
        lsum[s] = ls;
        idx_out[row * NSTAGE + s] = (float)bi;
    }

#pragma unroll
    for (int d = 0; d < EDIM; d += 4) {
        float4 v = make_float4(xq[d], xq[d + 1], xq[d + 2], xq[d + 3]);
        *reinterpret_cast<float4*>(&xq_aligned[row * EDIM + d]) = v;
        xq_out[row * EDIM + d + 0] = xq[d + 0];
        xq_out[row * EDIM + d + 1] = xq[d + 1];
        xq_out[row * EDIM + d + 2] = xq[d + 2];
        xq_out[row * EDIM + d + 3] = xq[d + 3];
    }

#pragma unroll
    for (int s = 0; s < NSTAGE; s++) {
        float v = lsum[s];
#pragma unroll
        for (int o = 16; o > 0; o >>= 1)
            v += __shfl_down_sync(0xffffffffu, v, o);
        if ((tid & 31) == 0) atomicAdd(&loss_accum[s], v);
    }
}

__global__ void zero_loss(float* acc)
{
    if (threadIdx.x < NSTAGE) acc[threadIdx.x] = 0.f;
}

__global__ void finalize_loss(const float* __restrict__ acc, float* __restrict__ out_loss)
{
    if (threadIdx.x == 0) {
        float t = acc[0] + acc[1] + acc[2] + acc[3];
        *out_loss = t * (1.25f / (4.0f * (float)BATCH * (float)EDIM));
    }
}

// ---------------------------------------------------------------------------
// Launch
// ---------------------------------------------------------------------------
extern "C" void kernel_launch(void* const* d_in, const int* in_sizes, int n_in,
                              void* d_out, int out_size)
{
    float* scratch = nullptr;
    cudaGetSymbolAddress((void**)&scratch, g_scratch);
    if (!scratch) return;

    const float* x   = (const float*)d_in[0];
    const float* ew0 = (const float*)d_in[1];
    const float* eb0 = (const float*)d_in[2];
    const float* ew1 = (const float*)d_in[3];
    const float* eb1 = (const float*)d_in[4];
    const float* ew2 = (const float*)d_in[5];
    const float* eb2 = (const float*)d_in[6];
    const float* ew3 = (const float*)d_in[7];
    const float* eb3 = (const float*)d_in[8];
    const float* dw0 = (const float*)d_in[9];
    const float* db0 = (const float*)d_in[10];
    const float* dw1 = (const float*)d_in[11];
    const float* db1 = (const float*)d_in[12];
    const float* dw2 = (const float*)d_in[13];
    const float* db2 = (const float*)d_in[14];
    const float* dw3 = (const float*)d_in[15];
    const float* db3 = (const float*)d_in[16];
    const float* cbs = (const float*)d_in[17];

    float* out = (float*)d_out;

    float* slotP0 = scratch;                          // B*512
    float* slotP1 = slotP0 + (size_t)BATCH * 512;     // B*512
    float* slotP2 = slotP1 + (size_t)BATCH * 512;     // B*512
    float* slotZ  = slotP2 + (size_t)BATCH * 512;     // B*32
    float* slotZQ = slotZ + (size_t)BATCH * 32;       // B*32
    float* lacc   = slotZQ + (size_t)BATCH * 32;      // 4

    float* y0  = slotP0;
    float* q0  = slotP1;
    float* q1  = slotP1 + (size_t)BATCH * 256;
    float* y1  = q0;
    float* y2  = slotP2;
    float* z   = slotZ;
    float* zq  = slotZQ;
    float* d1r = slotP2;   // dec0 out (B*128)
    float* d2r = slotP1;   // dec1 out (B*256)
    float* d3r = slotP0;   // dec2 out (B*512)

    float* out_main = out;                            // B*768 (16B aligned)
    float* out_loss = out + (size_t)BATCH * 768;      // 1
    float* out_idx  = out_loss + 1;                   // B*4  (4B aligned)
    float* out_xq   = out_idx + (size_t)BATCH * 4;    // B*32 (4B aligned)

    const int MB = BATCH / 128;  // 512 row-blocks

    zero_loss<<<1, 32>>>(lacc);

    // ---- Encoder (bit-exact KC=256 chunk path; gemm_db preserves bits) ----
    gemm_db<128, 128, 16, 8, 8, false, false><<<dim3(4, MB), 256>>>(
        x + 0,   768, ew0 + 0,   768, nullptr, slotP0, BATCH, 512, 256);
    gemm_db<128, 128, 16, 8, 8, false, false><<<dim3(4, MB), 256>>>(
        x + 256, 768, ew0 + 256, 768, nullptr, slotP1, BATCH, 512, 256);
    gemm_db<128, 128, 16, 8, 8, false, false><<<dim3(4, MB), 256>>>(
        x + 512, 768, ew0 + 512, 768, nullptr, slotP2, BATCH, 512, 256);
    combine3_relu<<<(BATCH * 512 + 255) / 256, 256>>>(
        slotP0, slotP1, slotP2, eb0, BATCH * 512, 512);

    gemm_db<128, 128, 16, 8, 8, false, false><<<dim3(2, MB), 256>>>(
        y0 + 0,   512, ew1 + 0,   512, nullptr, q0, BATCH, 256, 256);
    gemm_db<128, 128, 16, 8, 8, false, false><<<dim3(2, MB), 256>>>(
        y0 + 256, 512, ew1 + 256, 512, nullptr, q1, BATCH, 256, 256);
    combine2_relu<<<(BATCH * 256 + 255) / 256, 256>>>(
        q0, q1, eb1, BATCH * 256, 256);

    gemm_db<128, 128, 16, 8, 8, true, true><<<dim3(1, MB), 256>>>(
        y1, 256, ew2, 256, eb2, y2, BATCH, 128, 256);
    gemm_db<128, 32, 16, 8, 4, false, true><<<dim3(1, MB), 128>>>(
        y2, 128, ew3, 128, eb3, z, BATCH, 32, 128);

    // ---- Residual VQ (frozen) ----
    vq_kernel<<<BATCH / 256, 256>>>(z, cbs, zq, out_xq, out_idx, lacc);
    finalize_loss<<<1, 32>>>(lacc, out_loss);

    // ---- Decoder (SIMT, double-buffered) ----
    gemm_db<128, 128, 16, 8, 8, true, true><<<dim3(1, MB), 256>>>(
        zq, 32, dw0, 32, db0, d1r, BATCH, 128, 32);
    gemm_db<128, 128, 16, 8, 8, true, true><<<dim3(2, MB), 256>>>(
        d1r, 128, dw1, 128, db1, d2r, BATCH, 256, 128);
    gemm_db<128, 128, 16, 8, 8, true, true><<<dim3(4, MB), 256>>>(
        d2r, 256, dw2, 256, db2, d3r, BATCH, 512, 256);
    gemm_db<128, 128, 16, 8, 8, false, true><<<dim3(6, MB), 256>>>(
        d3r, 512, dw3, 512, db3, out_main, BATCH, 768, 512);
}